// round 14
// baseline (speedup 1.0000x reference)
#include <cuda_runtime.h>
#include <cuda_bf16.h>

// Problem constants
#define BB   512
#define LL   16384
#define NW   (LL - 5 + 1)          // 16380 windows

// Tiling (main kernel): 8 windows per lane, 256 elements per warp.
#define TPB  128                   // 4 warps
#define SEGW 256                   // elements per warp
#define CW   1024                  // windows per block
#define NWCH (LL / CW)             // 16 window chunks
#define NBCH 74                    // batch chunks (6/7-row slices)
#define MAXR 7                     // fixed unrolled trip count (gated)
#define NBLK (NWCH * NBCH)         // 1184 blocks = 148 SMs x 8 -> one full wave
#define NBLKP 1280                 // padded partial count (multiple of 128)
#define NVW  512                   // validity words: 16380 bits

// Packed mask/target: 4 elems per byte (low nibble = m bits, high = t&m bits).
#define PKW  (BB * LL / 16)        // 524288 uint32 words = 2 MiB
#define PKROW_U16 (LL / 8)         // 2048 ushorts per batch row

// Deterministic scratch (no cudaMalloc allowed).
__device__ unsigned     g_pk[PKW];        // packed t/m bits (2 MiB, L2-resident)
__device__ float        g_sq_blk[NBLKP];  // per-block sq partial (padding stays 0)
__device__ unsigned     g_vld_or[NVW];    // bit-per-window validity (OR-accum);
                                          // zeroed by last block each launch
__device__ unsigned int g_done;           // arrival counter; atomicInc wraps
                                          // at NBLK-1 -> self-resets per launch

__device__ __forceinline__ float sigm(float x0, float x1) {
    // softmax(x)[...,1] == sigmoid(x1-x0) == 1/(1+exp(x0-x1))
    return __fdividef(1.0f, 1.0f + __expf(x0 - x1));
}

// ---- Kernel A: pack tgt/msk (64 MiB) into 2-bit-per-elem form (2 MiB) ----
__global__ __launch_bounds__(256)
void bcl_pack(const int* __restrict__ tgt, const int* __restrict__ msk)
{
    const int j = blockIdx.x * 256 + threadIdx.x;   // 0..PKW-1 (grid 2048x256)
    const int4* t4 = (const int4*)tgt + 4 * j;
    const int4* m4 = (const int4*)msk + 4 * j;
    unsigned w = 0u;
#pragma unroll
    for (int k = 0; k < 4; k++) {
        int4 t = t4[k];
        int4 m = m4[k];
        unsigned b = (unsigned)((m.x & 1) | ((m.y & 1) << 1)
                   | ((m.z & 1) << 2) | ((m.w & 1) << 3)
                   | ((t.x & m.x & 1) << 4) | ((t.y & m.y & 1) << 5)
                   | ((t.z & m.z & 1) << 6) | ((t.w & m.w & 1) << 7));
        w |= b << (8 * k);
    }
    g_pk[j] = w;
}

// ---- Kernel B: windows from pred (64 MiB) + packed bits (L2) ----
__global__ __launch_bounds__(TPB, 8)
void bcl_fused(const float* __restrict__ pred,
               float*       __restrict__ out)
{
    const int lane = threadIdx.x & 31;
    const int wrp  = threadIdx.x >> 5;
    const int seg  = blockIdx.x * CW + wrp * SEGW;  // warp's first elem/window
    const int bch  = blockIdx.y;
    const int eo   = seg + 8 * lane;                // lane's first elem/window
    const bool blk_halo = (seg + SEGW) < LL;        // halo elems exist?
    const int hofs4 = blk_halo ? (SEGW / 2) : 0;    // float4 idx of elem seg+256
    const int hofsP = blk_halo ? 32 : 0;            // ushort idx of elem seg+256

    // Uneven batch slice (68 x 7 rows + 6 x 6 rows = 512), executed as a
    // FIXED 7-iteration unrolled loop; iteration >= nrows is mask-gated to a
    // mathematical no-op (reads row b1-adjacent, always in bounds).
    const int b0    = (bch * BB) / NBCH;
    const int nrows = ((bch + 1) * BB) / NBCH - b0;

    float accA = 0.f, accB = 0.f;                   // windows k<4 / k>=4
    unsigned vmask = 0u;

    const float4* fp4 = (const float4*)(pred + 2 * ((size_t)b0 * LL + seg));
    const unsigned short* pks =
        (const unsigned short*)g_pk + (size_t)b0 * PKROW_U16 + (seg >> 3);

#pragma unroll
    for (int bi = 0; bi < MAXR; bi++) {
        const unsigned gate = (bi < nrows) ? 0xFFFFu : 0u;  // 0 -> no-op iter
        // Own loads: 4 pred vectors + 1 packed ushort (16 bits = 8 elems).
        float4 v0 = fp4[4 * lane];
        float4 v1 = fp4[4 * lane + 1];
        float4 v2 = fp4[4 * lane + 2];
        float4 v3 = fp4[4 * lane + 3];
        unsigned pw = (unsigned)pks[lane];
        // Warp-edge halo (uniform broadcast; used only by lane 31).
        float4 hv0 = fp4[hofs4], hv1 = fp4[hofs4 + 1];
        unsigned hw = (unsigned)pks[hofsP];

        pw &= gate;
        hw &= blk_halo ? gate : 0u;

        // Derived per element: p = sigmoid; mm = m + 32*(t&m); pm = p*m; q = p^2*m
        float p[8], mm[8], pm[8], q[8];
        p[0] = sigm(v0.x, v0.y); p[1] = sigm(v0.z, v0.w);
        p[2] = sigm(v1.x, v1.y); p[3] = sigm(v1.z, v1.w);
        p[4] = sigm(v2.x, v2.y); p[5] = sigm(v2.z, v2.w);
        p[6] = sigm(v3.x, v3.y); p[7] = sigm(v3.z, v3.w);
#pragma unroll
        for (int e = 0; e < 8; e++) {
            const int sh  = (e >> 2) * 8 + (e & 3);
            int mi  = (int)((pw >> sh) & 1u);
            int tmi = (int)((pw >> (sh + 4)) & 1u);
            mm[e] = (float)(mi + (tmi << 5));
            pm[e] = mi ? p[e] : 0.f;
            q[e]  = p[e] * pm[e];
        }

        // Neighbor's first 4 derived values via shfl (convergent).
        float nmm[4], npm[4], nq[4];
#pragma unroll
        for (int k = 0; k < 4; k++) {
            nmm[k] = __shfl_down_sync(0xffffffffu, mm[k], 1);
            npm[k] = __shfl_down_sync(0xffffffffu, pm[k], 1);
            nq[k]  = __shfl_down_sync(0xffffffffu, q[k], 1);
        }
        // Lane 31 patches its halo from the warp-edge loads (low byte of hw).
        if (lane == 31) {
            float hp[4];
            hp[0] = sigm(hv0.x, hv0.y); hp[1] = sigm(hv0.z, hv0.w);
            hp[2] = sigm(hv1.x, hv1.y); hp[3] = sigm(hv1.z, hv1.w);
#pragma unroll
            for (int k = 0; k < 4; k++) {
                int mi  = (int)((hw >> k) & 1u);
                int tmi = (int)((hw >> (k + 4)) & 1u);
                nmm[k] = (float)(mi + (tmi << 5));
                npm[k] = mi ? hp[k] : 0.f;
                nq[k]  = hp[k] * npm[k];
            }
        }

        // Sliding window-5 over 12 elems {mm[0..7], nmm[0..3]}, incremental.
        float smm = mm[0] + mm[1] + mm[2] + mm[3] + mm[4];
        float spm = pm[0] + pm[1] + pm[2] + pm[3] + pm[4];
        float sq  = q[0]  + q[1]  + q[2]  + q[3]  + q[4];
#pragma unroll
        for (int k = 0; k < 8; k++) {
            if (k > 0) {
                float am = (k + 4 < 8) ? mm[k + 4] : nmm[k - 4];
                float ap = (k + 4 < 8) ? pm[k + 4] : npm[k - 4];
                float aq = (k + 4 < 8) ? q[k + 4]  : nq[k - 4];
                smm += am - mm[k - 1];
                spm += ap - pm[k - 1];
                sq  += aq - q[k - 1];
            }
            // msum integer-valued: pvar = sq/denom - pmean^2; tvar = tmean(1-tmean)
            float stm   = floorf(smm * 0.03125f);
            float sm    = fmaf(-32.0f, stm, smm);
            float denom = fmaxf(sm, 1.0f);
            float rd    = __fdividef(1.0f, denom);
            float pmean = spm * rd;
            float tmean = stm * rd;
            float pvar  = fmaf(-pmean, pmean, sq * rd);
            float tvar  = fmaf(-tmean, tmean, tmean);
            float d     = pvar - tvar;
            if (k < 4) accA = fmaf(d, d, accA);
            else       accB = fmaf(d, d, accB);
            if (sm > 0.f) vmask |= (1u << k);
        }

        fp4 += (LL / 2); pks += PKROW_U16;
    }

    // Tail gating: the ONLY OOB windows are eo=16376 (lane 31, warp 3,
    // block 15), positions k=4..7 — exactly accB.
    if (eo + 4 >= NW) { accB = 0.f; vmask &= 0x0Fu; }

    // Validity: one atomicOr per thread (RED.OR, order-independent ->
    // deterministic). eo is a multiple of 8, so the 8 bits never straddle.
    if (vmask)
        atomicOr(&g_vld_or[(unsigned)eo >> 5], vmask << ((unsigned)eo & 31u));
    __threadfence();   // this thread's REDs visible before block arrival

    // In-block deterministic reduction of sq -> one float per block.
    float a = accA + accB;
    a += __shfl_xor_sync(0xffffffffu, a, 16);
    a += __shfl_xor_sync(0xffffffffu, a, 8);
    a += __shfl_xor_sync(0xffffffffu, a, 4);
    a += __shfl_xor_sync(0xffffffffu, a, 2);
    a += __shfl_xor_sync(0xffffffffu, a, 1);
    __shared__ float s_red[4];
    __shared__ unsigned s_last;
    if (lane == 0) s_red[wrp] = a;
    __syncthreads();
    if (threadIdx.x == 0) {
        g_sq_blk[bch * NWCH + blockIdx.x] =
            (s_red[0] + s_red[1]) + (s_red[2] + s_red[3]);
        __threadfence();   // partial visible before arrival
        // Wrapping arrival counter: self-resets to 0 after NBLK increments.
        unsigned old = atomicInc(&g_done, NBLK - 1);
        s_last = (old == NBLK - 1) ? 1u : 0u;
    }
    __syncthreads();
    if (!s_last) return;

    // ---- Last block: final reduction (5 KB sq + 2 KB validity) ----
    __threadfence();       // acquire: all other blocks' fenced writes visible
    const int t = threadIdx.x;

    float s = 0.f;
#pragma unroll
    for (int i = 0; i < NBLKP / 128; i++)
        s += g_sq_blk[t + 128 * i];            // padding reads are 0

    uint4 vv = ((const uint4*)g_vld_or)[t];    // 512 words / 128 thr
    int c = __popc(vv.x) + __popc(vv.y) + __popc(vv.z) + __popc(vv.w);
    // Zero validity accumulator for the next graph replay.
    ((uint4*)g_vld_or)[t] = make_uint4(0u, 0u, 0u, 0u);

    // Block reduce s and c.
    s += __shfl_xor_sync(0xffffffffu, s, 16);
    s += __shfl_xor_sync(0xffffffffu, s, 8);
    s += __shfl_xor_sync(0xffffffffu, s, 4);
    s += __shfl_xor_sync(0xffffffffu, s, 2);
    s += __shfl_xor_sync(0xffffffffu, s, 1);
    c += __shfl_xor_sync(0xffffffffu, c, 16);
    c += __shfl_xor_sync(0xffffffffu, c, 8);
    c += __shfl_xor_sync(0xffffffffu, c, 4);
    c += __shfl_xor_sync(0xffffffffu, c, 2);
    c += __shfl_xor_sync(0xffffffffu, c, 1);
    __shared__ float fs[4];
    __shared__ int   fc[4];
    if (lane == 0) { fs[wrp] = s; fc[wrp] = c; }
    __syncthreads();
    if (t == 0) {
        float S = (fs[0] + fs[1]) + (fs[2] + fs[3]);
        int   C = (fc[0] + fc[1]) + (fc[2] + fc[3]);
        out[0] = S * (1.0f / (float)BB) / fmaxf((float)C, 1.0f);
    }
}

extern "C" void kernel_launch(void* const* d_in, const int* in_sizes, int n_in,
                              void* d_out, int out_size)
{
    const float* pred = (const float*)d_in[0];   // [512, 16384, 2] f32
    const int*   tgt  = (const int*)d_in[1];     // [512, 16384] i32
    const int*   msk  = (const int*)d_in[2];     // [512, 16384] i32

    bcl_pack<<<PKW / 256, 256>>>(tgt, msk);       // 64 MiB -> 2 MiB (L2)
    dim3 grid(NWCH, NBCH);                        // 16 x 74 = 1184 = 148 x 8
    bcl_fused<<<grid, TPB>>>(pred, (float*)d_out);
}

// round 15
// speedup vs baseline: 1.1837x; 1.1837x over previous
#include <cuda_runtime.h>
#include <cuda_bf16.h>

// Problem constants
#define BB   512
#define LL   16384
#define NW   (LL - 5 + 1)          // 16380 windows

// Tiling: 8 windows per lane, 256 elements per warp.
#define TPB  128                   // 4 warps
#define SEGW 256                   // elements per warp
#define CW   1024                  // windows per block
#define NWCH (LL / CW)             // 16 window chunks
#define NBCH 74                    // batch chunks (6/7-row slices)
#define MAXR 7                     // fixed unrolled trip count (gated)
#define NBLK (NWCH * NBCH)         // 1184 blocks = 148 SMs x 8 -> one full wave
#define NBLKP 1280                 // padded partial count (multiple of 128)
#define NVW  512                   // validity words: 16380 bits
#define SLOT 80                    // padded smem slot (64B data + 16B pad)

// Deterministic scratch (no cudaMalloc allowed).
__device__ float        g_sq_blk[NBLKP];  // per-block sq partial (padding stays 0)
__device__ unsigned     g_vld_or[NVW];    // bit-per-window validity (OR-accum);
                                          // zeroed by last block each launch
__device__ unsigned int g_done;           // arrival counter; atomicInc wraps
                                          // at NBLK-1 -> self-resets per launch

__device__ __forceinline__ float sigm(float x0, float x1) {
    // softmax(x)[...,1] == sigmoid(x1-x0) == 1/(1+exp(x0-x1))
    return __fdividef(1.0f, 1.0f + __expf(x0 - x1));
}

#define CP16(dst, src) \
    asm volatile("cp.async.cg.shared.global [%0], [%1], 16;" \
                 :: "r"(dst), "l"(src) : "memory")
#define CP_COMMIT() asm volatile("cp.async.commit_group;" ::: "memory")
#define CP_WAIT1()  asm volatile("cp.async.wait_group 1;"  ::: "memory")

__global__ __launch_bounds__(TPB, 8)
void bcl_fused(const float* __restrict__ pred,
               const int*   __restrict__ tgt,
               const int*   __restrict__ msk,
               float*       __restrict__ out)
{
    const int lane = threadIdx.x & 31;
    const int wrp  = threadIdx.x >> 5;
    const int seg  = blockIdx.x * CW + wrp * SEGW;  // warp's first elem/window
    const int bch  = blockIdx.y;
    const int eo   = seg + 8 * lane;                // lane's first elem/window
    const bool blk_halo = (seg + SEGW) < LL;        // halo elems exist?
    const int hofs4 = blk_halo ? (SEGW / 2) : 0;    // float4 idx of elem seg+256
    const int hofsT = blk_halo ? (SEGW / 4) : 0;    // int4 idx of elem seg+256

    // 2-stage cp.async pipeline for pred: per-lane 64B into 80B-padded slots
    // (conflict-free LDS.128 readback; each lane reads only its own slot).
    __shared__ __align__(16) char s_pred[2][4][32 * SLOT];

    // Uneven batch slice (68 x 7 rows + 6 x 6 rows = 512), FIXED 7-iteration
    // unrolled loop; iteration >= nrows is mask-gated to a no-op (reads an
    // always-in-bounds dummy row).
    const int b0    = (bch * BB) / NBCH;
    const int nrows = ((bch + 1) * BB) / NBCH - b0;

    float accA = 0.f, accB = 0.f;                   // windows k<4 / k>=4
    unsigned vmask = 0u;

    const float4* fp4 = (const float4*)(pred + 2 * ((size_t)b0 * LL + seg));
    const int4*   t4p = (const int4*)(tgt + (size_t)b0 * LL + seg);
    const int4*   m4p = (const int4*)(msk + (size_t)b0 * LL + seg);

    const unsigned sb[2] = {
        (unsigned)__cvta_generic_to_shared(&s_pred[0][wrp][SLOT * lane]),
        (unsigned)__cvta_generic_to_shared(&s_pred[1][wrp][SLOT * lane])
    };

    // Prologue: stage 0 <- row b0.
    {
        const char* g = (const char*)fp4 + 64 * lane;
        CP16(sb[0],      g);
        CP16(sb[0] + 16, g + 16);
        CP16(sb[0] + 32, g + 32);
        CP16(sb[0] + 48, g + 48);
        CP_COMMIT();
    }

#pragma unroll
    for (int bi = 0; bi < MAXR; bi++) {
        const int gate = (bi < nrows) ? -1 : 0;     // 0 -> no-op iteration
        const float4* fp4n = fp4 + (LL / 2);

        // Prefetch next row's pred into the other stage.
        if (bi < MAXR - 1) {
            const char* g = (const char*)fp4n + 64 * lane;
            const unsigned d = sb[(bi + 1) & 1];
            CP16(d,      g);
            CP16(d + 16, g + 16);
            CP16(d + 32, g + 32);
            CP16(d + 48, g + 48);
        }
        CP_COMMIT();
        CP_WAIT1();   // current stage's group complete (per-thread, own data)

        // tgt/msk own loads (direct LDG) + uniform halo loads.
        int4   tv0 = t4p[2 * lane],     tv1 = t4p[2 * lane + 1];
        int4   mv0 = m4p[2 * lane],     mv1 = m4p[2 * lane + 1];
        float4 hv0 = fp4[hofs4], hv1 = fp4[hofs4 + 1];
        int4   htv = t4p[hofsT], hmv = m4p[hofsT];

        mv0.x &= gate; mv0.y &= gate; mv0.z &= gate; mv0.w &= gate;
        mv1.x &= gate; mv1.y &= gate; mv1.z &= gate; mv1.w &= gate;
        const int hgate = blk_halo ? gate : 0;
        hmv.x &= hgate; hmv.y &= hgate; hmv.z &= hgate; hmv.w &= hgate;

        // Own pred from smem (4x LDS.128, conflict-free via 80B slot stride).
        const float4* sv = (const float4*)&s_pred[bi & 1][wrp][SLOT * lane];
        float4 v0 = sv[0], v1 = sv[1], v2 = sv[2], v3 = sv[3];

        // Derived per element: p = sigmoid; mm = m + 32*(t&m); pm = p*m; q = p^2*m
        float p[8], mm[8], pm[8], q[8];
        p[0] = sigm(v0.x, v0.y); p[1] = sigm(v0.z, v0.w);
        p[2] = sigm(v1.x, v1.y); p[3] = sigm(v1.z, v1.w);
        p[4] = sigm(v2.x, v2.y); p[5] = sigm(v2.z, v2.w);
        p[6] = sigm(v3.x, v3.y); p[7] = sigm(v3.z, v3.w);
        const int tt[8] = {tv0.x, tv0.y, tv0.z, tv0.w, tv1.x, tv1.y, tv1.z, tv1.w};
        const int mi[8] = {mv0.x, mv0.y, mv0.z, mv0.w, mv1.x, mv1.y, mv1.z, mv1.w};
#pragma unroll
        for (int e = 0; e < 8; e++) {
            mm[e] = (float)(mi[e] + ((tt[e] & mi[e]) << 5));
            pm[e] = mi[e] ? p[e] : 0.f;
            q[e]  = p[e] * pm[e];
        }

        // Neighbor's first 4 derived values via shfl (convergent).
        float nmm[4], npm[4], nq[4];
#pragma unroll
        for (int k = 0; k < 4; k++) {
            nmm[k] = __shfl_down_sync(0xffffffffu, mm[k], 1);
            npm[k] = __shfl_down_sync(0xffffffffu, pm[k], 1);
            nq[k]  = __shfl_down_sync(0xffffffffu, q[k], 1);
        }
        // Lane 31 patches its halo from the warp-edge loads.
        if (lane == 31) {
            float hp[4];
            hp[0] = sigm(hv0.x, hv0.y); hp[1] = sigm(hv0.z, hv0.w);
            hp[2] = sigm(hv1.x, hv1.y); hp[3] = sigm(hv1.z, hv1.w);
            const int ht[4] = {htv.x, htv.y, htv.z, htv.w};
            const int hm[4] = {hmv.x, hmv.y, hmv.z, hmv.w};
#pragma unroll
            for (int k = 0; k < 4; k++) {
                nmm[k] = (float)(hm[k] + ((ht[k] & hm[k]) << 5));
                npm[k] = hm[k] ? hp[k] : 0.f;
                nq[k]  = hp[k] * npm[k];
            }
        }

        // Sliding window-5 over 12 elems {mm[0..7], nmm[0..3]}, incremental.
        float smm = mm[0] + mm[1] + mm[2] + mm[3] + mm[4];
        float spm = pm[0] + pm[1] + pm[2] + pm[3] + pm[4];
        float sq  = q[0]  + q[1]  + q[2]  + q[3]  + q[4];
#pragma unroll
        for (int k = 0; k < 8; k++) {
            if (k > 0) {
                float am = (k + 4 < 8) ? mm[k + 4] : nmm[k - 4];
                float ap = (k + 4 < 8) ? pm[k + 4] : npm[k - 4];
                float aq = (k + 4 < 8) ? q[k + 4]  : nq[k - 4];
                smm += am - mm[k - 1];
                spm += ap - pm[k - 1];
                sq  += aq - q[k - 1];
            }
            // msum integer-valued: pvar = sq/denom - pmean^2; tvar = tmean(1-tmean)
            float stm   = floorf(smm * 0.03125f);
            float sm    = fmaf(-32.0f, stm, smm);
            float denom = fmaxf(sm, 1.0f);
            float rd    = __fdividef(1.0f, denom);
            float pmean = spm * rd;
            float tmean = stm * rd;
            float pvar  = fmaf(-pmean, pmean, sq * rd);
            float tvar  = fmaf(-tmean, tmean, tmean);
            float d     = pvar - tvar;
            if (k < 4) accA = fmaf(d, d, accA);
            else       accB = fmaf(d, d, accB);
            if (sm > 0.f) vmask |= (1u << k);
        }

        fp4 = fp4n; t4p += (LL / 4); m4p += (LL / 4);
    }

    // Tail gating: the ONLY OOB windows are eo=16376 (lane 31, warp 3,
    // block 15), positions k=4..7 — exactly accB.
    if (eo + 4 >= NW) { accB = 0.f; vmask &= 0x0Fu; }

    // Validity: one atomicOr per thread (RED.OR, order-independent ->
    // deterministic). eo is a multiple of 8, so the 8 bits never straddle.
    if (vmask)
        atomicOr(&g_vld_or[(unsigned)eo >> 5], vmask << ((unsigned)eo & 31u));
    __threadfence();   // this thread's REDs visible before block arrival

    // In-block deterministic reduction of sq -> one float per block.
    float a = accA + accB;
    a += __shfl_xor_sync(0xffffffffu, a, 16);
    a += __shfl_xor_sync(0xffffffffu, a, 8);
    a += __shfl_xor_sync(0xffffffffu, a, 4);
    a += __shfl_xor_sync(0xffffffffu, a, 2);
    a += __shfl_xor_sync(0xffffffffu, a, 1);
    __shared__ float s_red[4];
    __shared__ unsigned s_last;
    if (lane == 0) s_red[wrp] = a;
    __syncthreads();
    if (threadIdx.x == 0) {
        g_sq_blk[bch * NWCH + blockIdx.x] =
            (s_red[0] + s_red[1]) + (s_red[2] + s_red[3]);
        __threadfence();   // partial visible before arrival
        // Wrapping arrival counter: self-resets to 0 after NBLK increments.
        unsigned old = atomicInc(&g_done, NBLK - 1);
        s_last = (old == NBLK - 1) ? 1u : 0u;
    }
    __syncthreads();
    if (!s_last) return;

    // ---- Last block: final reduction (5 KB sq + 2 KB validity) ----
    __threadfence();       // acquire: all other blocks' fenced writes visible
    const int t = threadIdx.x;

    float s = 0.f;
#pragma unroll
    for (int i = 0; i < NBLKP / 128; i++)
        s += g_sq_blk[t + 128 * i];            // padding reads are 0

    uint4 vv = ((const uint4*)g_vld_or)[t];    // 512 words / 128 thr
    int c = __popc(vv.x) + __popc(vv.y) + __popc(vv.z) + __popc(vv.w);
    // Zero validity accumulator for the next graph replay.
    ((uint4*)g_vld_or)[t] = make_uint4(0u, 0u, 0u, 0u);

    // Block reduce s and c.
    s += __shfl_xor_sync(0xffffffffu, s, 16);
    s += __shfl_xor_sync(0xffffffffu, s, 8);
    s += __shfl_xor_sync(0xffffffffu, s, 4);
    s += __shfl_xor_sync(0xffffffffu, s, 2);
    s += __shfl_xor_sync(0xffffffffu, s, 1);
    c += __shfl_xor_sync(0xffffffffu, c, 16);
    c += __shfl_xor_sync(0xffffffffu, c, 8);
    c += __shfl_xor_sync(0xffffffffu, c, 4);
    c += __shfl_xor_sync(0xffffffffu, c, 2);
    c += __shfl_xor_sync(0xffffffffu, c, 1);
    __shared__ float fs[4];
    __shared__ int   fc[4];
    if (lane == 0) { fs[wrp] = s; fc[wrp] = c; }
    __syncthreads();
    if (t == 0) {
        float S = (fs[0] + fs[1]) + (fs[2] + fs[3]);
        int   C = (fc[0] + fc[1]) + (fc[2] + fc[3]);
        out[0] = S * (1.0f / (float)BB) / fmaxf((float)C, 1.0f);
    }
}

extern "C" void kernel_launch(void* const* d_in, const int* in_sizes, int n_in,
                              void* d_out, int out_size)
{
    const float* pred = (const float*)d_in[0];   // [512, 16384, 2] f32
    const int*   tgt  = (const int*)d_in[1];     // [512, 16384] i32
    const int*   msk  = (const int*)d_in[2];     // [512, 16384] i32

    dim3 grid(NWCH, NBCH);                        // 16 x 74 = 1184 = 148 x 8
    bcl_fused<<<grid, TPB>>>(pred, tgt, msk, (float*)d_out);
}

// round 16
// speedup vs baseline: 1.3708x; 1.1581x over previous
#include <cuda_runtime.h>
#include <cuda_bf16.h>

// Problem constants
#define BB   512
#define LL   16384
#define NW   (LL - 5 + 1)          // 16380 windows

// Tiling: 8 windows per lane, 256 elements per warp (R10 peak config).
#define TPB  128                   // 4 warps
#define SEGW 256                   // elements per warp
#define CW   1024                  // windows per block
#define NWCH (LL / CW)             // 16 window chunks
#define BC   8                     // batches per block
#define NBCH (BB / BC)             // 64 batch chunks
#define NBLK (NWCH * NBCH)         // 1024 blocks -> single wave @ 8/SM
#define NVW  512                   // validity words: 16380 bits

// Deterministic scratch (no cudaMalloc allowed).
__device__ float        g_sq_blk[NBLK];   // per-block sq partial (4 KB)
__device__ unsigned     g_vld_or[NVW];    // bit-per-window validity (OR-accum);
                                          // zeroed by last block each launch
__device__ unsigned int g_done;           // arrival counter; atomicInc wraps
                                          // at NBLK-1 -> self-resets per launch

__device__ __forceinline__ float sigm(float x0, float x1) {
    // softmax(x)[...,1] == sigmoid(x1-x0) == 1/(1+exp(x0-x1))
    return __fdividef(1.0f, 1.0f + __expf(x0 - x1));
}

__global__ __launch_bounds__(TPB, 8)
void bcl_fused(const float* __restrict__ pred,
               const int*   __restrict__ tgt,
               const int*   __restrict__ msk,
               float*       __restrict__ out)
{
    const int lane = threadIdx.x & 31;
    const int wrp  = threadIdx.x >> 5;
    const int seg  = blockIdx.x * CW + wrp * SEGW;  // warp's first elem/window
    const int bch  = blockIdx.y;
    const int eo   = seg + 8 * lane;                // lane's first elem/window
    const bool blk_halo = (seg + SEGW) < LL;        // halo elems exist?
    const int hofs4 = blk_halo ? (SEGW / 2) : 0;    // float4 idx of elem seg+256
    const int hofsT = blk_halo ? (SEGW / 4) : 0;    // int4 idx of elem seg+256

    float accA = 0.f, accB = 0.f;                   // windows k<4 / k>=4
    unsigned vmask = 0u;

    const size_t eb0 = (size_t)(bch * BC) * LL + seg;
    const float4* fp4 = (const float4*)(pred + 2 * eb0);
    const int4*   t4p = (const int4*)(tgt + eb0);
    const int4*   m4p = (const int4*)(msk + eb0);

#pragma unroll
    for (int bi = 0; bi < BC; bi++) {
        // Own loads: lane owns 8 consecutive elems; evict-first streaming
        // (each line touched exactly once by its owning warp).
        float4 v0 = __ldcs(fp4 + 4 * lane);
        float4 v1 = __ldcs(fp4 + 4 * lane + 1);
        float4 v2 = __ldcs(fp4 + 4 * lane + 2);
        float4 v3 = __ldcs(fp4 + 4 * lane + 3);
        int4   tv0 = __ldcs(t4p + 2 * lane), tv1 = __ldcs(t4p + 2 * lane + 1);
        int4   mv0 = __ldcs(m4p + 2 * lane), mv1 = __ldcs(m4p + 2 * lane + 1);
        // Warp-edge halo (uniform broadcast, default caching — L1 reuse).
        float4 hv0 = fp4[hofs4], hv1 = fp4[hofs4 + 1];
        int4   htv = t4p[hofsT], hmv = m4p[hofsT];
        if (!blk_halo) { hmv.x = 0; hmv.y = 0; hmv.z = 0; hmv.w = 0; }

        // Derived per element: p = sigmoid; mm = m + 32*(t&m); pm = p*m; q = p^2*m
        float p[8], mm[8], pm[8], q[8];
        p[0] = sigm(v0.x, v0.y); p[1] = sigm(v0.z, v0.w);
        p[2] = sigm(v1.x, v1.y); p[3] = sigm(v1.z, v1.w);
        p[4] = sigm(v2.x, v2.y); p[5] = sigm(v2.z, v2.w);
        p[6] = sigm(v3.x, v3.y); p[7] = sigm(v3.z, v3.w);
        const int tt[8] = {tv0.x, tv0.y, tv0.z, tv0.w, tv1.x, tv1.y, tv1.z, tv1.w};
        const int mi[8] = {mv0.x, mv0.y, mv0.z, mv0.w, mv1.x, mv1.y, mv1.z, mv1.w};
#pragma unroll
        for (int e = 0; e < 8; e++) {
            mm[e] = (float)(mi[e] + ((tt[e] & mi[e]) << 5));
            pm[e] = mi[e] ? p[e] : 0.f;
            q[e]  = p[e] * pm[e];
        }

        // Neighbor's first 4 derived values via shfl (convergent).
        float nmm[4], npm[4], nq[4];
#pragma unroll
        for (int k = 0; k < 4; k++) {
            nmm[k] = __shfl_down_sync(0xffffffffu, mm[k], 1);
            npm[k] = __shfl_down_sync(0xffffffffu, pm[k], 1);
            nq[k]  = __shfl_down_sync(0xffffffffu, q[k], 1);
        }
        // Lane 31 patches its halo from the warp-edge loads.
        if (lane == 31) {
            float hp[4];
            hp[0] = sigm(hv0.x, hv0.y); hp[1] = sigm(hv0.z, hv0.w);
            hp[2] = sigm(hv1.x, hv1.y); hp[3] = sigm(hv1.z, hv1.w);
            const int ht[4] = {htv.x, htv.y, htv.z, htv.w};
            const int hm[4] = {hmv.x, hmv.y, hmv.z, hmv.w};
#pragma unroll
            for (int k = 0; k < 4; k++) {
                nmm[k] = (float)(hm[k] + ((ht[k] & hm[k]) << 5));
                npm[k] = hm[k] ? hp[k] : 0.f;
                nq[k]  = hp[k] * npm[k];
            }
        }

        // Sliding window-5 over 12 elems {mm[0..7], nmm[0..3]}, incremental.
        float smm = mm[0] + mm[1] + mm[2] + mm[3] + mm[4];
        float spm = pm[0] + pm[1] + pm[2] + pm[3] + pm[4];
        float sq  = q[0]  + q[1]  + q[2]  + q[3]  + q[4];
#pragma unroll
        for (int k = 0; k < 8; k++) {
            if (k > 0) {
                float am = (k + 4 < 8) ? mm[k + 4] : nmm[k - 4];
                float ap = (k + 4 < 8) ? pm[k + 4] : npm[k - 4];
                float aq = (k + 4 < 8) ? q[k + 4]  : nq[k - 4];
                smm += am - mm[k - 1];
                spm += ap - pm[k - 1];
                sq  += aq - q[k - 1];
            }
            // msum integer-valued: pvar = sq/denom - pmean^2; tvar = tmean(1-tmean)
            float stm   = floorf(smm * 0.03125f);
            float sm    = fmaf(-32.0f, stm, smm);
            float denom = fmaxf(sm, 1.0f);
            float rd    = __fdividef(1.0f, denom);
            float pmean = spm * rd;
            float tmean = stm * rd;
            float pvar  = fmaf(-pmean, pmean, sq * rd);
            float tvar  = fmaf(-tmean, tmean, tmean);
            float d     = pvar - tvar;
            if (k < 4) accA = fmaf(d, d, accA);
            else       accB = fmaf(d, d, accB);
            if (sm > 0.f) vmask |= (1u << k);
        }

        fp4 += (LL / 2); t4p += (LL / 4); m4p += (LL / 4);
    }

    // Tail gating: the ONLY OOB windows are eo=16376 (lane 31, warp 3,
    // block 15), positions k=4..7 — exactly accB.
    if (eo + 4 >= NW) { accB = 0.f; vmask &= 0x0Fu; }

    // Validity: one atomicOr per thread (RED.OR, order-independent ->
    // deterministic). eo is a multiple of 8, so the 8 bits never straddle.
    if (vmask)
        atomicOr(&g_vld_or[(unsigned)eo >> 5], vmask << ((unsigned)eo & 31u));
    __threadfence();   // this thread's REDs visible before block arrival

    // In-block deterministic reduction of sq -> one float per block.
    float a = accA + accB;
    a += __shfl_xor_sync(0xffffffffu, a, 16);
    a += __shfl_xor_sync(0xffffffffu, a, 8);
    a += __shfl_xor_sync(0xffffffffu, a, 4);
    a += __shfl_xor_sync(0xffffffffu, a, 2);
    a += __shfl_xor_sync(0xffffffffu, a, 1);
    __shared__ float s_red[4];
    __shared__ unsigned s_last;
    if (lane == 0) s_red[wrp] = a;
    __syncthreads();
    if (threadIdx.x == 0) {
        g_sq_blk[bch * NWCH + blockIdx.x] =
            (s_red[0] + s_red[1]) + (s_red[2] + s_red[3]);
        __threadfence();   // partial visible before arrival
        // Wrapping arrival counter: self-resets to 0 after NBLK increments.
        unsigned old = atomicInc(&g_done, NBLK - 1);
        s_last = (old == NBLK - 1) ? 1u : 0u;
    }
    __syncthreads();
    if (!s_last) return;

    // ---- Last block: final reduction (4 KB sq + 2 KB validity) ----
    __threadfence();       // acquire: all other blocks' fenced writes visible
    const int t = threadIdx.x;

    float s = 0.f;
    const float4* sq4 = (const float4*)g_sq_blk;   // 1024 floats = 256 float4
#pragma unroll
    for (int i = 0; i < 2; i++) {
        float4 v = sq4[t + 128 * i];
        s += (v.x + v.y) + (v.z + v.w);
    }
    uint4 vv = ((const uint4*)g_vld_or)[t];        // 512 words / 128 thr
    int c = __popc(vv.x) + __popc(vv.y) + __popc(vv.z) + __popc(vv.w);
    // Zero validity accumulator for the next graph replay.
    ((uint4*)g_vld_or)[t] = make_uint4(0u, 0u, 0u, 0u);

    // Block reduce s and c.
    s += __shfl_xor_sync(0xffffffffu, s, 16);
    s += __shfl_xor_sync(0xffffffffu, s, 8);
    s += __shfl_xor_sync(0xffffffffu, s, 4);
    s += __shfl_xor_sync(0xffffffffu, s, 2);
    s += __shfl_xor_sync(0xffffffffu, s, 1);
    c += __shfl_xor_sync(0xffffffffu, c, 16);
    c += __shfl_xor_sync(0xffffffffu, c, 8);
    c += __shfl_xor_sync(0xffffffffu, c, 4);
    c += __shfl_xor_sync(0xffffffffu, c, 2);
    c += __shfl_xor_sync(0xffffffffu, c, 1);
    __shared__ float fs[4];
    __shared__ int   fc[4];
    if (lane == 0) { fs[wrp] = s; fc[wrp] = c; }
    __syncthreads();
    if (t == 0) {
        float S = (fs[0] + fs[1]) + (fs[2] + fs[3]);
        int   C = (fc[0] + fc[1]) + (fc[2] + fc[3]);
        out[0] = S * (1.0f / (float)BB) / fmaxf((float)C, 1.0f);
    }
}

extern "C" void kernel_launch(void* const* d_in, const int* in_sizes, int n_in,
                              void* d_out, int out_size)
{
    const float* pred = (const float*)d_in[0];   // [512, 16384, 2] f32
    const int*   tgt  = (const int*)d_in[1];     // [512, 16384] i32
    const int*   msk  = (const int*)d_in[2];     // [512, 16384] i32

    dim3 grid(NWCH, NBCH);                        // 16 x 64 = 1024 blocks
    bcl_fused<<<grid, TPB>>>(pred, tgt, msk, (float*)d_out);
}

// round 17
// speedup vs baseline: 1.3724x; 1.0011x over previous
#include <cuda_runtime.h>
#include <cuda_bf16.h>

// Problem constants
#define BB   512
#define LL   16384
#define NW   (LL - 5 + 1)          // 16380 windows

// Tiling: 8 windows per lane, 256 elements per warp.
#define TPB  128                   // 4 warps
#define SEGW 256                   // elements per warp
#define CW   1024                  // windows per block
#define NWCH (LL / CW)             // 16 window chunks
#define NBCH 74                    // batch chunks (6/7-row slices)
#define MAXR 7                     // fixed unrolled trip count (gated)
#define NBLK (NWCH * NBCH)         // 1184 blocks = 148 SMs x 8 -> one full wave
#define NBLKP 1280                 // padded partial count (multiple of 128)
#define NVW  512                   // validity words: 16380 bits

// Deterministic scratch (no cudaMalloc allowed).
__device__ float        g_sq_blk[NBLKP];  // per-block sq partial (padding stays 0)
__device__ unsigned     g_vld_or[NVW];    // bit-per-window validity (OR-accum);
                                          // zeroed by last block each launch
__device__ unsigned int g_done;           // arrival counter; atomicInc wraps
                                          // at NBLK-1 -> self-resets per launch

__device__ __forceinline__ float sigm(float x0, float x1) {
    // softmax(x)[...,1] == sigmoid(x1-x0) == 1/(1+exp(x0-x1))
    return __fdividef(1.0f, 1.0f + __expf(x0 - x1));
}

__global__ __launch_bounds__(TPB, 8)
void bcl_fused(const float* __restrict__ pred,
               const int*   __restrict__ tgt,
               const int*   __restrict__ msk,
               float*       __restrict__ out)
{
    const int lane = threadIdx.x & 31;
    const int wrp  = threadIdx.x >> 5;
    const int seg  = blockIdx.x * CW + wrp * SEGW;  // warp's first elem/window
    const int bch  = blockIdx.y;
    const int eo   = seg + 8 * lane;                // lane's first elem/window
    const bool blk_halo = (seg + SEGW) < LL;        // halo elems exist?
    const int hofs4 = blk_halo ? (SEGW / 2) : 0;    // float4 idx of elem seg+256
    const int hofsT = blk_halo ? (SEGW / 4) : 0;    // int4 idx of elem seg+256

    // Uneven batch slice (68 x 7 rows + 6 x 6 rows = 512), executed as a
    // FIXED 7-iteration unrolled loop; iteration >= nrows is mask-gated to a
    // mathematical no-op (reads an always-in-bounds dummy row).
    const int b0    = (bch * BB) / NBCH;
    const int nrows = ((bch + 1) * BB) / NBCH - b0;

    float accA = 0.f, accB = 0.f;                   // windows k<4 / k>=4
    unsigned vmask = 0u;

    const size_t eb0 = (size_t)b0 * LL + seg;
    const float4* fp4 = (const float4*)(pred + 2 * eb0);
    const int4*   t4p = (const int4*)(tgt + eb0);
    const int4*   m4p = (const int4*)(msk + eb0);

#pragma unroll
    for (int bi = 0; bi < MAXR; bi++) {
        const int gate = (bi < nrows) ? -1 : 0;     // 0 -> no-op iteration
        // Own loads: lane owns 8 consecutive elems; evict-first streaming
        // (each line touched exactly once by its owning warp, once per run).
        float4 v0 = __ldcs(fp4 + 4 * lane);
        float4 v1 = __ldcs(fp4 + 4 * lane + 1);
        float4 v2 = __ldcs(fp4 + 4 * lane + 2);
        float4 v3 = __ldcs(fp4 + 4 * lane + 3);
        int4   tv0 = __ldcs(t4p + 2 * lane), tv1 = __ldcs(t4p + 2 * lane + 1);
        int4   mv0 = __ldcs(m4p + 2 * lane), mv1 = __ldcs(m4p + 2 * lane + 1);
        // Warp-edge halo (uniform broadcast, default caching — L1 reuse).
        float4 hv0 = fp4[hofs4], hv1 = fp4[hofs4 + 1];
        int4   htv = t4p[hofsT], hmv = m4p[hofsT];

        // Gate masks: dummy iteration (or missing halo) contributes zero.
        mv0.x &= gate; mv0.y &= gate; mv0.z &= gate; mv0.w &= gate;
        mv1.x &= gate; mv1.y &= gate; mv1.z &= gate; mv1.w &= gate;
        const int hgate = blk_halo ? gate : 0;
        hmv.x &= hgate; hmv.y &= hgate; hmv.z &= hgate; hmv.w &= hgate;

        // Derived per element: p = sigmoid; mm = m + 32*(t&m); pm = p*m; q = p^2*m
        float p[8], mm[8], pm[8], q[8];
        p[0] = sigm(v0.x, v0.y); p[1] = sigm(v0.z, v0.w);
        p[2] = sigm(v1.x, v1.y); p[3] = sigm(v1.z, v1.w);
        p[4] = sigm(v2.x, v2.y); p[5] = sigm(v2.z, v2.w);
        p[6] = sigm(v3.x, v3.y); p[7] = sigm(v3.z, v3.w);
        const int tt[8] = {tv0.x, tv0.y, tv0.z, tv0.w, tv1.x, tv1.y, tv1.z, tv1.w};
        const int mi[8] = {mv0.x, mv0.y, mv0.z, mv0.w, mv1.x, mv1.y, mv1.z, mv1.w};
#pragma unroll
        for (int e = 0; e < 8; e++) {
            mm[e] = (float)(mi[e] + ((tt[e] & mi[e]) << 5));
            pm[e] = mi[e] ? p[e] : 0.f;
            q[e]  = p[e] * pm[e];
        }

        // Neighbor's first 4 derived values via shfl (convergent).
        float nmm[4], npm[4], nq[4];
#pragma unroll
        for (int k = 0; k < 4; k++) {
            nmm[k] = __shfl_down_sync(0xffffffffu, mm[k], 1);
            npm[k] = __shfl_down_sync(0xffffffffu, pm[k], 1);
            nq[k]  = __shfl_down_sync(0xffffffffu, q[k], 1);
        }
        // Lane 31 patches its halo from the warp-edge loads.
        if (lane == 31) {
            float hp[4];
            hp[0] = sigm(hv0.x, hv0.y); hp[1] = sigm(hv0.z, hv0.w);
            hp[2] = sigm(hv1.x, hv1.y); hp[3] = sigm(hv1.z, hv1.w);
            const int ht[4] = {htv.x, htv.y, htv.z, htv.w};
            const int hm[4] = {hmv.x, hmv.y, hmv.z, hmv.w};
#pragma unroll
            for (int k = 0; k < 4; k++) {
                nmm[k] = (float)(hm[k] + ((ht[k] & hm[k]) << 5));
                npm[k] = hm[k] ? hp[k] : 0.f;
                nq[k]  = hp[k] * npm[k];
            }
        }

        // Sliding window-5 over 12 elems {mm[0..7], nmm[0..3]}, incremental.
        float smm = mm[0] + mm[1] + mm[2] + mm[3] + mm[4];
        float spm = pm[0] + pm[1] + pm[2] + pm[3] + pm[4];
        float sq  = q[0]  + q[1]  + q[2]  + q[3]  + q[4];
#pragma unroll
        for (int k = 0; k < 8; k++) {
            if (k > 0) {
                float am = (k + 4 < 8) ? mm[k + 4] : nmm[k - 4];
                float ap = (k + 4 < 8) ? pm[k + 4] : npm[k - 4];
                float aq = (k + 4 < 8) ? q[k + 4]  : nq[k - 4];
                smm += am - mm[k - 1];
                spm += ap - pm[k - 1];
                sq  += aq - q[k - 1];
            }
            // msum integer-valued: pvar = sq/denom - pmean^2; tvar = tmean(1-tmean)
            float stm   = floorf(smm * 0.03125f);
            float sm    = fmaf(-32.0f, stm, smm);
            float denom = fmaxf(sm, 1.0f);
            float rd    = __fdividef(1.0f, denom);
            float pmean = spm * rd;
            float tmean = stm * rd;
            float pvar  = fmaf(-pmean, pmean, sq * rd);
            float tvar  = fmaf(-tmean, tmean, tmean);
            float d     = pvar - tvar;
            if (k < 4) accA = fmaf(d, d, accA);
            else       accB = fmaf(d, d, accB);
            if (sm > 0.f) vmask |= (1u << k);
        }

        fp4 += (LL / 2); t4p += (LL / 4); m4p += (LL / 4);
    }

    // Tail gating: the ONLY OOB windows are eo=16376 (lane 31, warp 3,
    // block 15), positions k=4..7 — exactly accB.
    if (eo + 4 >= NW) { accB = 0.f; vmask &= 0x0Fu; }

    // Validity: one atomicOr per thread (RED.OR, order-independent ->
    // deterministic). eo is a multiple of 8, so the 8 bits never straddle.
    if (vmask)
        atomicOr(&g_vld_or[(unsigned)eo >> 5], vmask << ((unsigned)eo & 31u));
    __threadfence();   // this thread's REDs visible before block arrival

    // In-block deterministic reduction of sq -> one float per block.
    float a = accA + accB;
    a += __shfl_xor_sync(0xffffffffu, a, 16);
    a += __shfl_xor_sync(0xffffffffu, a, 8);
    a += __shfl_xor_sync(0xffffffffu, a, 4);
    a += __shfl_xor_sync(0xffffffffu, a, 2);
    a += __shfl_xor_sync(0xffffffffu, a, 1);
    __shared__ float s_red[4];
    __shared__ unsigned s_last;
    if (lane == 0) s_red[wrp] = a;
    __syncthreads();
    if (threadIdx.x == 0) {
        g_sq_blk[bch * NWCH + blockIdx.x] =
            (s_red[0] + s_red[1]) + (s_red[2] + s_red[3]);
        __threadfence();   // partial visible before arrival
        // Wrapping arrival counter: self-resets to 0 after NBLK increments.
        unsigned old = atomicInc(&g_done, NBLK - 1);
        s_last = (old == NBLK - 1) ? 1u : 0u;
    }
    __syncthreads();
    if (!s_last) return;

    // ---- Last block: final reduction (5 KB sq + 2 KB validity) ----
    __threadfence();       // acquire: all other blocks' fenced writes visible
    const int t = threadIdx.x;

    float s = 0.f;
#pragma unroll
    for (int i = 0; i < NBLKP / 128; i++)
        s += g_sq_blk[t + 128 * i];            // padding reads are 0

    uint4 vv = ((const uint4*)g_vld_or)[t];    // 512 words / 128 thr
    int c = __popc(vv.x) + __popc(vv.y) + __popc(vv.z) + __popc(vv.w);
    // Zero validity accumulator for the next graph replay.
    ((uint4*)g_vld_or)[t] = make_uint4(0u, 0u, 0u, 0u);

    // Block reduce s and c.
    s += __shfl_xor_sync(0xffffffffu, s, 16);
    s += __shfl_xor_sync(0xffffffffu, s, 8);
    s += __shfl_xor_sync(0xffffffffu, s, 4);
    s += __shfl_xor_sync(0xffffffffu, s, 2);
    s += __shfl_xor_sync(0xffffffffu, s, 1);
    c += __shfl_xor_sync(0xffffffffu, c, 16);
    c += __shfl_xor_sync(0xffffffffu, c, 8);
    c += __shfl_xor_sync(0xffffffffu, c, 4);
    c += __shfl_xor_sync(0xffffffffu, c, 2);
    c += __shfl_xor_sync(0xffffffffu, c, 1);
    __shared__ float fs[4];
    __shared__ int   fc[4];
    if (lane == 0) { fs[wrp] = s; fc[wrp] = c; }
    __syncthreads();
    if (t == 0) {
        float S = (fs[0] + fs[1]) + (fs[2] + fs[3]);
        int   C = (fc[0] + fc[1]) + (fc[2] + fc[3]);
        out[0] = S * (1.0f / (float)BB) / fmaxf((float)C, 1.0f);
    }
}

extern "C" void kernel_launch(void* const* d_in, const int* in_sizes, int n_in,
                              void* d_out, int out_size)
{
    const float* pred = (const float*)d_in[0];   // [512, 16384, 2] f32
    const int*   tgt  = (const int*)d_in[1];     // [512, 16384] i32
    const int*   msk  = (const int*)d_in[2];     // [512, 16384] i32

    dim3 grid(NWCH, NBCH);                        // 16 x 74 = 1184 = 148 x 8
    bcl_fused<<<grid, TPB>>>(pred, tgt, msk, (float*)d_out);
}